// round 12
// baseline (speedup 1.0000x reference)
#include <cuda_runtime.h>
#include <cuda_bf16.h>

// CTC forward, two tasks (PyTorch semantics: blank=0, mean of loss/target_len,
// zero_infinity). One block per (task, batch) = 64 blocks x 256 threads.
//
// R=2 extended-target slots per thread (one blank + one symbol) held as
// (mantissa in [1,2), int32 exponent) pairs -> no MUFU on the critical path.
// Cross-thread operand per step = left thread's slot-1 only (2 shuffles;
// warp boundary via double-buffered 8-byte smem slot). Stager threads
// (tid < C) pre-convert each logits row to linear probs (ex2 done once
// block-wide); consumers prefetch their 2 probs one step ahead.
// Phantom slots (l >= L) are never killed: they only feed higher l and can
// never reach the read positions 2*tlen-1, 2*tlen <= L-1.

#define LOG2E 1.4426950408889634f
#define LN2   0.6931471805599453f
#define BATCH 32
#define TMAX  2000
#define NT    256
#define EDEAD (-(1 << 28))

static __device__ float        g_partial[64];
static __device__ unsigned int g_count = 0;

__device__ __forceinline__ float ex2(float x) {
    float y; asm("ex2.approx.f32 %0, %1;" : "=f"(y) : "f"(x)); return y;
}
__device__ __forceinline__ float lg2(float x) {
    float y; asm("lg2.approx.f32 %0, %1;" : "=f"(y) : "f"(x)); return y;
}

__device__ __forceinline__ void upd3(float ma, int ea, float mb, int eb,
                                     float mc, int ec, float p,
                                     float& mo, int& eo) {
    int em = max(ea, max(eb, ec));
    float sa = __int_as_float(max(ea - em + 127, 0) << 23);
    float sb = __int_as_float(max(eb - em + 127, 0) << 23);
    float sc = __int_as_float(max(ec - em + 127, 0) << 23);
    float s  = fmaf(mc, sc, fmaf(mb, sb, ma * sa));   // [1,6)
    float mp = p * s;                                  // normal, >0
    int bb = __float_as_int(mp);
    eo = em + ((bb >> 23) - 127);
    mo = __int_as_float((bb & 0x007FFFFF) | 0x3F800000);
}
__device__ __forceinline__ void upd2(float ma, int ea, float mb, int eb,
                                     float p, float& mo, int& eo) {
    int em = max(ea, eb);
    float sa = __int_as_float(max(ea - em + 127, 0) << 23);
    float sb = __int_as_float(max(eb - em + 127, 0) << 23);
    float s  = fmaf(mb, sb, ma * sa);
    float mp = p * s;
    int bb = __float_as_int(mp);
    eo = em + ((bb >> 23) - 127);
    mo = __int_as_float((bb & 0x007FFFFF) | 0x3F800000);
}
__device__ __forceinline__ float pow2c(int dp127) {
    return __int_as_float(max(dp127, 0) << 23);
}
__device__ __forceinline__ float clamplp(float x) {   // keep p normal, NaN-safe
    return fminf(fmaxf(x, -60.f), 0.f);
}

__global__ void __launch_bounds__(NT, 1)
ctc_forward_kernel(const float* __restrict__ elog, const float* __restrict__ plog,
                   const int* __restrict__ etgt, const int* __restrict__ ptgt,
                   const int* __restrict__ eil,  const int* __restrict__ pil,
                   const int* __restrict__ etl,  const int* __restrict__ ptl,
                   float* __restrict__ out)
{
    __shared__ float sD[TMAX];        // log2 softmax denominator per timestep
    __shared__ float sStage[2][64];   // staged LINEAR prob rows (ex2 applied)
    __shared__ uint2 sBnd[2][8];      // per-warp lane31 slot-1 (m,e), dbl-buffered
    __shared__ float sFm[NT * 2];
    __shared__ int   sFe[NT * 2];
    __shared__ int   sLast;

    const int task = blockIdx.x >> 5;   // 0 = error (C=4), 1 = phoneme (C=64)
    const int b    = blockIdx.x & 31;
    const int tid  = threadIdx.x;
    const int lane = tid & 31;
    const int wid  = tid >> 5;

    const float* logits;
    const int*   targets;
    int C, S, ilen, tlen;
    if (task == 0) {
        C = 4;  S = 50;
        logits  = elog + (size_t)b * TMAX * 4;
        targets = etgt + b * 50;
        ilen = eil[b]; tlen = etl[b];
    } else {
        C = 64; S = 200;
        logits  = plog + (size_t)b * TMAX * 64;
        targets = ptgt + b * 200;
        ilen = pil[b]; tlen = ptl[b];
    }
    const int L     = 2 * S + 1;
    const int Teff  = min(TMAX, max(ilen, 1));
    const int rlast = Teff - 1;
    const bool warpLive = (64 * wid < L);

    // ---------- Phase 1: log2 softmax denominators ----------
    for (int t = tid; t < Teff; t += NT) {
        const float* row = logits + (size_t)t * C;
        float s = 0.f;
        for (int k = 0; k < C; k += 4) {
            float4 v = *reinterpret_cast<const float4*>(row + k);
            s += ex2(v.x * LOG2E) + ex2(v.y * LOG2E)
               + ex2(v.z * LOG2E) + ex2(v.w * LOG2E);
        }
        sD[t] = lg2(s);
    }
    __syncthreads();

    // ---------- Per-thread slot setup: l = 2*tid, 2*tid+1 ----------
    const int  ext1  = targets[min(tid, S - 1)];
    const bool skip1 = (tid >= 1) && (ext1 != targets[min(tid - 1, S - 1)]);

    // ---------- alpha init (t = 0) ----------
    float m0 = 1.f, m1 = 1.f;
    int   e0 = EDEAD, e1 = EDEAD;
    if (tid == 0) {
        float a = ex2(clamplp(fmaf(logits[0],    LOG2E, -sD[0])));
        int bb = __float_as_int(a);
        e0 = (bb >> 23) - 127; m0 = __int_as_float((bb & 0x007FFFFF) | 0x3F800000);
        a = ex2(clamplp(fmaf(logits[ext1], LOG2E, -sD[0])));
        bb = __float_as_int(a);
        e1 = (bb >> 23) - 127; m1 = __int_as_float((bb & 0x007FFFFF) | 0x3F800000);
    }
    if (lane == 31) sBnd[0][wid] = make_uint2(__float_as_uint(m1), (unsigned)e1);

    // Stage row 1 (linear probs); prefetch row 2 logits.
    float gpre = 0.f;
    if (tid < C) {
        int r1 = min(1, rlast);
        sStage[1][tid] = ex2(clamplp(fmaf(logits[(size_t)r1 * C + tid], LOG2E,
                                          -sD[r1])));
        gpre = logits[(size_t)min(2, rlast) * C + tid];
    }
    __syncthreads();

    float pb = sStage[1][0];
    float p1 = sStage[1][ext1];

    // ---------- Phase 2: forward scan, 1 step per barrier ----------
    #pragma unroll 2
    for (int t = 1; t < Teff; ++t) {
        const int bq = (t + 1) & 1;   // buffer for row t+1
        const int br = (t - 1) & 1;   // sBnd buffer holding state @ t-1
        const int bw = t & 1;         // sBnd buffer to write state @ t

        // Stager: convert row t+1 to linear probs; prefetch row t+2 logits.
        if (tid < C) {
            if (t + 1 < Teff)
                sStage[bq][tid] = ex2(clamplp(fmaf(gpre, LOG2E, -sD[t + 1])));
            if (t + 2 < Teff)
                gpre = logits[(size_t)(t + 2) * C + tid];
        }

        if (warpLive) {
            // left thread's OLD slot-1
            float nm = __shfl_up_sync(0xffffffffu, m1, 1);
            int   ne = __shfl_up_sync(0xffffffffu, e1, 1);
            if (lane == 0) {
                if (wid > 0) {
                    uint2 v = sBnd[br][wid - 1];
                    nm = __uint_as_float(v.x); ne = (int)v.y;
                } else { nm = 1.f; ne = EDEAD; }
            }

            float o0m, o1m; int o0e, o1e;
            upd2(m0, e0, nm, ne, pb, o0m, o0e);                          // blank
            upd3(m1, e1, m0, e0, nm, skip1 ? ne : EDEAD, p1, o1m, o1e);  // symbol
            m0 = o0m; e0 = o0e; m1 = o1m; e1 = o1e;

            if (lane == 31)
                sBnd[bw][wid] = make_uint2(__float_as_uint(m1), (unsigned)e1);
        }

        __syncthreads();

        // Prefetch probs for step t+1 (row already staged; off critical path).
        if (warpLive && (t + 1 < Teff)) {
            pb = sStage[bq][0];
            p1 = sStage[bq][ext1];
        }
    }

    // ---------- publish finals ----------
    sFm[2 * tid]     = m0; sFe[2 * tid]     = e0;
    sFm[2 * tid + 1] = m1; sFe[2 * tid + 1] = e1;
    __syncthreads();

    // ---------- loss + fused deterministic reduction ----------
    if (tid == 0) {
        const int iL = 2 * tlen - 1, iB = 2 * tlen;
        int   eL = sFe[iL], eB = sFe[iB];
        float mL = sFm[iL], mB = sFm[iB];
        int   em = max(eL, eB);
        float ss = mL * pow2c(eL + 127 - em) + mB * pow2c(eB + 127 - em);
        float loss = -((float)em + lg2(ss)) * LN2;
        if (em < -(1 << 27)) loss = 0.f;      // unreachable => inf => zeroed
        if (!(loss <= 1e29f)) loss = 0.f;     // zero_infinity / NaN
        g_partial[blockIdx.x] = loss / (float)tlen * (1.0f / BATCH);
        __threadfence();
        unsigned tk = atomicAdd(&g_count, 1u);
        sLast = (tk == 63u);
    }
    __syncthreads();
    if (sLast && tid == 0) {
        __threadfence();
        float s = 0.f;
        #pragma unroll
        for (int i = 0; i < 64; ++i) {
            float v;
            asm volatile("ld.global.cg.f32 %0, [%1];" : "=f"(v) : "l"(g_partial + i));
            s += v;
        }
        out[0] = s;
        g_count = 0;   // reset for graph replay
    }
}

extern "C" void kernel_launch(void* const* d_in, const int* in_sizes, int n_in,
                              void* d_out, int out_size)
{
    const float* elog = (const float*)d_in[0];
    const float* plog = (const float*)d_in[1];
    const int*   etgt = (const int*)d_in[2];
    const int*   ptgt = (const int*)d_in[3];
    const int*   eil  = (const int*)d_in[4];
    const int*   pil  = (const int*)d_in[5];
    const int*   etl  = (const int*)d_in[6];
    const int*   ptl  = (const int*)d_in[7];
    float* out = (float*)d_out;

    ctc_forward_kernel<<<64, NT>>>(elog, plog, etgt, ptgt,
                                   eil, pil, etl, ptl, out);
}